// round 15
// baseline (speedup 1.0000x reference)
#include <cuda_runtime.h>

namespace {

constexpr int Bc = 1024;
constexpr int Tc = 1024;
constexpr int Dc = 256;
constexpr int Mc = 10;
constexpr int ROWS = 4;
constexpr int CBLK = Bc / ROWS;                    // 256 compute blocks
constexpr int GRID = 1184;                         // 8 blocks/SM * 148 SMs
constexpr long long TOTAL4 = (long long)Bc * Tc * (Dc / 4);  // 64M float4
constexpr int UNIT = 4096;                         // float4 per ticket (64 KB)
constexpr unsigned NUNITS = (unsigned)(TOTAL4 / UNIT);       // 16384, exact

__device__ float    g_WkT[Dc * Dc];   // Wk transposed (rebuilt per launch)
__device__ unsigned g_ticket;         // copy work counter (reset per launch)

__device__ __forceinline__ float sigf(float v) {
    return 1.0f / (1.0f + __expf(-v));
}

// ---------------------------------------------------------------------------
// Kernel 0: transpose Wk into g_WkT; block (0,0) also resets the ticket.
// ---------------------------------------------------------------------------
__global__ __launch_bounds__(256) void bjrnn_prep(const float* __restrict__ Wk)
{
    if (blockIdx.x == 0 && blockIdx.y == 0 && threadIdx.x == 0)
        g_ticket = 0u;
    __shared__ float t[32][33];
    const int bx = blockIdx.x * 32, by = blockIdx.y * 32;
    const int tx = threadIdx.x & 31, ty = threadIdx.x >> 5;   // ty in [0,8)
    #pragma unroll
    for (int p = 0; p < 4; ++p)
        t[ty + p * 8][tx] = Wk[(by + ty + p * 8) * Dc + bx + tx];
    __syncthreads();
    #pragma unroll
    for (int p = 0; p < 4; ++p)
        g_WkT[(bx + ty + p * 8) * Dc + by + tx] = t[tx][ty + p * 8];
}

// ---------------------------------------------------------------------------
// Fused kernel: blocks [0,256) compute h/y/cur-slice for 4 batch rows each
// (H streamed from global twice — no smem stage), then ALL 1184 blocks pull
// 64KB copy units off a global ticket.
// ---------------------------------------------------------------------------
__global__ __launch_bounds__(256, 8) void bjrnn_fused(
    const float*  __restrict__ x,
    const float*  __restrict__ hist,
    const float*  __restrict__ Wi, const float* __restrict__ bi,
    const float*  __restrict__ Wv, const float* __restrict__ bv,
    const float*  __restrict__ Wb, const float* __restrict__ bb,
    const int*    __restrict__ jumps,
    const int*    __restrict__ curp,
    float* __restrict__ oh,       // [B, D]
    float* __restrict__ oy,       // [B, D]
    float* __restrict__ ohist)    // [B, T, D]
{
    __shared__ float xs [ROWS * Dc];     // x rows; reused as h after h-stage
    __shared__ float qs [ROWS * Dc];
    __shared__ float gs [ROWS * Dc];
    __shared__ float red[8 * ROWS * Mc];
    __shared__ float scs[ROWS * Mc];
    __shared__ float att[ROWS * Mc];
    __shared__ unsigned s_t;

    const int cur = __ldg(curp);
    const int j   = threadIdx.x;

    if (blockIdx.x < CBLK) {
        const int b0   = blockIdx.x * ROWS;
        const int lane = j & 31;
        const int warp = j >> 5;
        const long long HB = (long long)b0 * Tc * Dc;   // row base of batch b0
        const long long RS = (long long)Tc * Dc;        // stride between rows

        #pragma unroll
        for (int r = 0; r < ROWS; ++r)
            xs[r * Dc + j] = x[(b0 + r) * Dc + j];
        __syncthreads();

        // --- q = x @ Wi + bi (coalesced in j); park q in smem
        {
            float a0 = bi[j], a1 = a0, a2 = a0, a3 = a0;
            #pragma unroll 4
            for (int d = 0; d < Dc; ++d) {
                const float w = Wi[d * Dc + j];
                a0 = fmaf(xs[d],          w, a0);
                a1 = fmaf(xs[Dc + d],     w, a1);
                a2 = fmaf(xs[2 * Dc + d], w, a2);
                a3 = fmaf(xs[3 * Dc + d], w, a3);
            }
            qs[j] = a0; qs[Dc + j] = a1;
            qs[2 * Dc + j] = a2; qs[3 * Dc + j] = a3;
        }
        __syncthreads();

        // --- p[r][j] = sum_k Wk[j,k] q[r,k] via WkT (coalesced)
        float p0 = 0.f, p1 = 0.f, p2 = 0.f, p3 = 0.f;
        #pragma unroll 4
        for (int k = 0; k < Dc; ++k) {
            const float w = g_WkT[k * Dc + j];
            p0 = fmaf(qs[k],          w, p0);
            p1 = fmaf(qs[Dc + k],     w, p1);
            p2 = fmaf(qs[2 * Dc + k], w, p2);
            p3 = fmaf(qs[3 * Dc + k], w, p3);
        }

        // --- scores[r][m] = sum_j H[r,m,j] p[r,j]; H streamed from global
        #pragma unroll
        for (int m = 0; m < Mc; ++m) {
            int idx = cur - __ldg(&jumps[m]);
            idx = idx < 0 ? 0 : idx;
            const float* __restrict__ hb = hist + HB + (long long)idx * Dc + j;
            float v0 = __ldg(hb)          * p0;
            float v1 = __ldg(hb + RS)     * p1;
            float v2 = __ldg(hb + 2 * RS) * p2;
            float v3 = __ldg(hb + 3 * RS) * p3;
            #pragma unroll
            for (int o = 16; o; o >>= 1) {
                v0 += __shfl_xor_sync(0xFFFFFFFFu, v0, o);
                v1 += __shfl_xor_sync(0xFFFFFFFFu, v1, o);
                v2 += __shfl_xor_sync(0xFFFFFFFFu, v2, o);
                v3 += __shfl_xor_sync(0xFFFFFFFFu, v3, o);
            }
            if (lane == 0) {
                red[warp * (ROWS * Mc) + 0 * Mc + m] = v0;
                red[warp * (ROWS * Mc) + 1 * Mc + m] = v1;
                red[warp * (ROWS * Mc) + 2 * Mc + m] = v2;
                red[warp * (ROWS * Mc) + 3 * Mc + m] = v3;
            }
        }
        __syncthreads();
        if (j < ROWS * Mc) {      // 40 threads
            float s = 0.f;
            #pragma unroll
            for (int w = 0; w < 8; ++w) s += red[w * (ROWS * Mc) + j];
            scs[j] = s * (1.0f / 16.0f);      // / sqrt(256)
        }
        __syncthreads();
        if (j < ROWS) {           // per-row softmax over 10
            float mx = scs[j * Mc];
            #pragma unroll
            for (int m = 1; m < Mc; ++m) mx = fmaxf(mx, scs[j * Mc + m]);
            float e[Mc], es = 0.f;
            #pragma unroll
            for (int m = 0; m < Mc; ++m) {
                e[m] = __expf(scs[j * Mc + m] - mx);
                es += e[m];
            }
            const float inv = 1.0f / es;
            #pragma unroll
            for (int m = 0; m < Mc; ++m) att[j * Mc + m] = e[m] * inv;
        }
        __syncthreads();

        // --- g[r][j] = sum_m att[r][m] H[r,m,j]; H re-streamed (L2-hot)
        {
            float g0 = 0.f, g1 = 0.f, g2 = 0.f, g3 = 0.f;
            #pragma unroll
            for (int m = 0; m < Mc; ++m) {
                int idx = cur - __ldg(&jumps[m]);
                idx = idx < 0 ? 0 : idx;
                const float* __restrict__ hb =
                    hist + HB + (long long)idx * Dc + j;
                g0 = fmaf(att[0 * Mc + m], __ldg(hb),          g0);
                g1 = fmaf(att[1 * Mc + m], __ldg(hb + RS),     g1);
                g2 = fmaf(att[2 * Mc + m], __ldg(hb + 2 * RS), g2);
                g3 = fmaf(att[3 * Mc + m], __ldg(hb + 3 * RS), g3);
            }
            gs[j] = g0; gs[Dc + j] = g1;
            gs[2 * Dc + j] = g2; gs[3 * Dc + j] = g3;
        }
        __syncthreads();

        // --- rs = g @ Wv + bv ; h = sigmoid(q + rs)
        {
            float r0 = bv[j], r1 = r0, r2 = r0, r3 = r0;
            #pragma unroll 4
            for (int d = 0; d < Dc; ++d) {
                const float w = Wv[d * Dc + j];
                r0 = fmaf(gs[d],          w, r0);
                r1 = fmaf(gs[Dc + d],     w, r1);
                r2 = fmaf(gs[2 * Dc + d], w, r2);
                r3 = fmaf(gs[3 * Dc + d], w, r3);
            }
            const float h0 = sigf(qs[j]          + r0);
            const float h1 = sigf(qs[Dc + j]     + r1);
            const float h2 = sigf(qs[2 * Dc + j] + r2);
            const float h3 = sigf(qs[3 * Dc + j] + r3);
            __syncthreads();       // xs (x) reads all done; reuse as h
            xs[j] = h0; xs[Dc + j] = h1;
            xs[2 * Dc + j] = h2; xs[3 * Dc + j] = h3;
            oh[(b0 + 0) * Dc + j] = h0;
            oh[(b0 + 1) * Dc + j] = h1;
            oh[(b0 + 2) * Dc + j] = h2;
            oh[(b0 + 3) * Dc + j] = h3;
            float* __restrict__ oc = ohist + HB + (long long)cur * Dc + j;
            oc[0]      = h0;
            oc[RS]     = h1;
            oc[2 * RS] = h2;
            oc[3 * RS] = h3;
        }
        __syncthreads();

        // --- y = sigmoid(h @ Wb + bb + h)
        {
            float y0 = bb[j] + xs[j];
            float y1 = bb[j] + xs[Dc + j];
            float y2 = bb[j] + xs[2 * Dc + j];
            float y3 = bb[j] + xs[3 * Dc + j];
            #pragma unroll 4
            for (int d = 0; d < Dc; ++d) {
                const float w = Wb[d * Dc + j];
                y0 = fmaf(xs[d],          w, y0);
                y1 = fmaf(xs[Dc + d],     w, y1);
                y2 = fmaf(xs[2 * Dc + d], w, y2);
                y3 = fmaf(xs[3 * Dc + d], w, y3);
            }
            oy[(b0 + 0) * Dc + j] = sigf(y0);
            oy[(b0 + 1) * Dc + j] = sigf(y1);
            oy[(b0 + 2) * Dc + j] = sigf(y2);
            oy[(b0 + 3) * Dc + j] = sigf(y3);
        }
    }

    // ---------------- ticket-balanced streaming copy (all blocks) ----------
    const float4* __restrict__ src = reinterpret_cast<const float4*>(hist);
    float4*       __restrict__ dst = reinterpret_cast<float4*>(ohist);
    for (;;) {
        __syncthreads();
        if (j == 0) s_t = atomicAdd(&g_ticket, 1u);
        __syncthreads();
        const unsigned u = s_t;
        if (u >= NUNITS) break;
        const long long base = (long long)u * UNIT + j;
        #pragma unroll
        for (int q4 = 0; q4 < 4; ++q4) {
            const long long i0 = base + (q4 * 4 + 0) * 256;
            const long long i1 = base + (q4 * 4 + 1) * 256;
            const long long i2 = base + (q4 * 4 + 2) * 256;
            const long long i3 = base + (q4 * 4 + 3) * 256;
            const float4 v0 = __ldcs(src + i0);
            const float4 v1 = __ldcs(src + i1);
            const float4 v2 = __ldcs(src + i2);
            const float4 v3 = __ldcs(src + i3);
            if ((int)((i0 >> 6) & (Tc - 1)) != cur) __stcs(dst + i0, v0);
            if ((int)((i1 >> 6) & (Tc - 1)) != cur) __stcs(dst + i1, v1);
            if ((int)((i2 >> 6) & (Tc - 1)) != cur) __stcs(dst + i2, v2);
            if ((int)((i3 >> 6) & (Tc - 1)) != cur) __stcs(dst + i3, v3);
        }
    }
}

} // namespace

extern "C" void kernel_launch(void* const* d_in, const int* in_sizes, int n_in,
                              void* d_out, int out_size)
{
    const float* x    = (const float*)d_in[0];
    const float* hist = (const float*)d_in[1];
    const float* Wi   = (const float*)d_in[2];
    const float* bi   = (const float*)d_in[3];
    const float* Wk   = (const float*)d_in[4];
    // d_in[5] = bk — dropped: constant over m, softmax-shift invariant
    const float* Wv   = (const float*)d_in[6];
    const float* bv   = (const float*)d_in[7];
    const float* Wb   = (const float*)d_in[8];
    const float* bb   = (const float*)d_in[9];
    const int*   jp   = (const int*)d_in[10];
    const int*   cur  = (const int*)d_in[11];

    float* out   = (float*)d_out;
    float* oh    = out;                    // h:  [B, D]
    float* oy    = out + Bc * Dc;          // y:  [B, D]
    float* ohist = out + 2 * Bc * Dc;      // new_history: [B, T, D]

    (void)in_sizes; (void)n_in; (void)out_size;

    // 0) transpose Wk + reset copy ticket (graph-replay safe)
    bjrnn_prep<<<dim3(Dc / 32, Dc / 32), 256>>>(Wk);

    // 1) fused compute + ticket-balanced full-occupancy copy
    bjrnn_fused<<<GRID, 256>>>(
        x, hist, Wi, bi, Wv, bv, Wb, bb, jp, cur, oh, oy, ohist);
}

// round 16
// speedup vs baseline: 1.0072x; 1.0072x over previous
#include <cuda_runtime.h>

namespace {

constexpr int Bc = 1024;
constexpr int Tc = 1024;
constexpr int Dc = 256;
constexpr int Mc = 10;
constexpr int ROWS = 4;
constexpr int CBLK = Bc / ROWS;                    // 256 compute blocks
constexpr int GRID = 1184;                         // 8 blocks/SM * 148 SMs
constexpr long long TOTAL4 = (long long)Bc * Tc * (Dc / 4);  // 64M float4
constexpr int UNIT = 4096;                         // float4 per ticket (64 KB)
constexpr unsigned NUNITS = (unsigned)(TOTAL4 / UNIT);       // 16384, exact

__device__ float    g_WkT[Dc * Dc];   // Wk transposed (rebuilt per launch)
__device__ unsigned g_ticket;         // copy work counter (reset per launch)

__device__ __forceinline__ float sigf(float v) {
    return 1.0f / (1.0f + __expf(-v));
}

// ---------------------------------------------------------------------------
// Kernel 0: transpose Wk into g_WkT; block (0,0) also resets the ticket.
// ---------------------------------------------------------------------------
__global__ __launch_bounds__(256) void bjrnn_prep(const float* __restrict__ Wk)
{
    if (blockIdx.x == 0 && blockIdx.y == 0 && threadIdx.x == 0)
        g_ticket = 0u;
    __shared__ float t[32][33];
    const int bx = blockIdx.x * 32, by = blockIdx.y * 32;
    const int tx = threadIdx.x & 31, ty = threadIdx.x >> 5;   // ty in [0,8)
    #pragma unroll
    for (int p = 0; p < 4; ++p)
        t[ty + p * 8][tx] = Wk[(by + ty + p * 8) * Dc + bx + tx];
    __syncthreads();
    #pragma unroll
    for (int p = 0; p < 4; ++p)
        g_WkT[(bx + ty + p * 8) * Dc + by + tx] = t[tx][ty + p * 8];
}

// ---------------------------------------------------------------------------
// Fused kernel: blocks [0,256) compute h/y/cur-slice for 4 batch rows each
// (H streamed from global twice — no smem stage), then ALL 1184 blocks pull
// 64KB copy units off a global ticket.
// ---------------------------------------------------------------------------
__global__ __launch_bounds__(256, 8) void bjrnn_fused(
    const float*  __restrict__ x,
    const float*  __restrict__ hist,
    const float*  __restrict__ Wi, const float* __restrict__ bi,
    const float*  __restrict__ Wv, const float* __restrict__ bv,
    const float*  __restrict__ Wb, const float* __restrict__ bb,
    const int*    __restrict__ jumps,
    const int*    __restrict__ curp,
    float* __restrict__ oh,       // [B, D]
    float* __restrict__ oy,       // [B, D]
    float* __restrict__ ohist)    // [B, T, D]
{
    __shared__ float xs [ROWS * Dc];     // x rows; reused as h after h-stage
    __shared__ float qs [ROWS * Dc];
    __shared__ float gs [ROWS * Dc];
    __shared__ float red[8 * ROWS * Mc];
    __shared__ float scs[ROWS * Mc];
    __shared__ float att[ROWS * Mc];
    __shared__ unsigned s_t;

    const int cur = __ldg(curp);
    const int j   = threadIdx.x;

    if (blockIdx.x < CBLK) {
        const int b0   = blockIdx.x * ROWS;
        const int lane = j & 31;
        const int warp = j >> 5;
        const long long HB = (long long)b0 * Tc * Dc;   // row base of batch b0
        const long long RS = (long long)Tc * Dc;        // stride between rows

        #pragma unroll
        for (int r = 0; r < ROWS; ++r)
            xs[r * Dc + j] = x[(b0 + r) * Dc + j];
        __syncthreads();

        // --- q = x @ Wi + bi (coalesced in j); park q in smem
        {
            float a0 = bi[j], a1 = a0, a2 = a0, a3 = a0;
            #pragma unroll 4
            for (int d = 0; d < Dc; ++d) {
                const float w = Wi[d * Dc + j];
                a0 = fmaf(xs[d],          w, a0);
                a1 = fmaf(xs[Dc + d],     w, a1);
                a2 = fmaf(xs[2 * Dc + d], w, a2);
                a3 = fmaf(xs[3 * Dc + d], w, a3);
            }
            qs[j] = a0; qs[Dc + j] = a1;
            qs[2 * Dc + j] = a2; qs[3 * Dc + j] = a3;
        }
        __syncthreads();

        // --- p[r][j] = sum_k Wk[j,k] q[r,k] via WkT (coalesced)
        float p0 = 0.f, p1 = 0.f, p2 = 0.f, p3 = 0.f;
        #pragma unroll 4
        for (int k = 0; k < Dc; ++k) {
            const float w = g_WkT[k * Dc + j];
            p0 = fmaf(qs[k],          w, p0);
            p1 = fmaf(qs[Dc + k],     w, p1);
            p2 = fmaf(qs[2 * Dc + k], w, p2);
            p3 = fmaf(qs[3 * Dc + k], w, p3);
        }

        // --- scores[r][m] = sum_j H[r,m,j] p[r,j]; H streamed from global
        #pragma unroll
        for (int m = 0; m < Mc; ++m) {
            int idx = cur - __ldg(&jumps[m]);
            idx = idx < 0 ? 0 : idx;
            const float* __restrict__ hb = hist + HB + (long long)idx * Dc + j;
            float v0 = __ldg(hb)          * p0;
            float v1 = __ldg(hb + RS)     * p1;
            float v2 = __ldg(hb + 2 * RS) * p2;
            float v3 = __ldg(hb + 3 * RS) * p3;
            #pragma unroll
            for (int o = 16; o; o >>= 1) {
                v0 += __shfl_xor_sync(0xFFFFFFFFu, v0, o);
                v1 += __shfl_xor_sync(0xFFFFFFFFu, v1, o);
                v2 += __shfl_xor_sync(0xFFFFFFFFu, v2, o);
                v3 += __shfl_xor_sync(0xFFFFFFFFu, v3, o);
            }
            if (lane == 0) {
                red[warp * (ROWS * Mc) + 0 * Mc + m] = v0;
                red[warp * (ROWS * Mc) + 1 * Mc + m] = v1;
                red[warp * (ROWS * Mc) + 2 * Mc + m] = v2;
                red[warp * (ROWS * Mc) + 3 * Mc + m] = v3;
            }
        }
        __syncthreads();
        if (j < ROWS * Mc) {      // 40 threads
            float s = 0.f;
            #pragma unroll
            for (int w = 0; w < 8; ++w) s += red[w * (ROWS * Mc) + j];
            scs[j] = s * (1.0f / 16.0f);      // / sqrt(256)
        }
        __syncthreads();
        if (j < ROWS) {           // per-row softmax over 10
            float mx = scs[j * Mc];
            #pragma unroll
            for (int m = 1; m < Mc; ++m) mx = fmaxf(mx, scs[j * Mc + m]);
            float e[Mc], es = 0.f;
            #pragma unroll
            for (int m = 0; m < Mc; ++m) {
                e[m] = __expf(scs[j * Mc + m] - mx);
                es += e[m];
            }
            const float inv = 1.0f / es;
            #pragma unroll
            for (int m = 0; m < Mc; ++m) att[j * Mc + m] = e[m] * inv;
        }
        __syncthreads();

        // --- g[r][j] = sum_m att[r][m] H[r,m,j]; H re-streamed (L2-hot)
        {
            float g0 = 0.f, g1 = 0.f, g2 = 0.f, g3 = 0.f;
            #pragma unroll
            for (int m = 0; m < Mc; ++m) {
                int idx = cur - __ldg(&jumps[m]);
                idx = idx < 0 ? 0 : idx;
                const float* __restrict__ hb =
                    hist + HB + (long long)idx * Dc + j;
                g0 = fmaf(att[0 * Mc + m], __ldg(hb),          g0);
                g1 = fmaf(att[1 * Mc + m], __ldg(hb + RS),     g1);
                g2 = fmaf(att[2 * Mc + m], __ldg(hb + 2 * RS), g2);
                g3 = fmaf(att[3 * Mc + m], __ldg(hb + 3 * RS), g3);
            }
            gs[j] = g0; gs[Dc + j] = g1;
            gs[2 * Dc + j] = g2; gs[3 * Dc + j] = g3;
        }
        __syncthreads();

        // --- rs = g @ Wv + bv ; h = sigmoid(q + rs)
        {
            float r0 = bv[j], r1 = r0, r2 = r0, r3 = r0;
            #pragma unroll 4
            for (int d = 0; d < Dc; ++d) {
                const float w = Wv[d * Dc + j];
                r0 = fmaf(gs[d],          w, r0);
                r1 = fmaf(gs[Dc + d],     w, r1);
                r2 = fmaf(gs[2 * Dc + d], w, r2);
                r3 = fmaf(gs[3 * Dc + d], w, r3);
            }
            const float h0 = sigf(qs[j]          + r0);
            const float h1 = sigf(qs[Dc + j]     + r1);
            const float h2 = sigf(qs[2 * Dc + j] + r2);
            const float h3 = sigf(qs[3 * Dc + j] + r3);
            __syncthreads();       // xs (x) reads all done; reuse as h
            xs[j] = h0; xs[Dc + j] = h1;
            xs[2 * Dc + j] = h2; xs[3 * Dc + j] = h3;
            oh[(b0 + 0) * Dc + j] = h0;
            oh[(b0 + 1) * Dc + j] = h1;
            oh[(b0 + 2) * Dc + j] = h2;
            oh[(b0 + 3) * Dc + j] = h3;
            float* __restrict__ oc = ohist + HB + (long long)cur * Dc + j;
            oc[0]      = h0;
            oc[RS]     = h1;
            oc[2 * RS] = h2;
            oc[3 * RS] = h3;
        }
        __syncthreads();

        // --- y = sigmoid(h @ Wb + bb + h)
        {
            float y0 = bb[j] + xs[j];
            float y1 = bb[j] + xs[Dc + j];
            float y2 = bb[j] + xs[2 * Dc + j];
            float y3 = bb[j] + xs[3 * Dc + j];
            #pragma unroll 4
            for (int d = 0; d < Dc; ++d) {
                const float w = Wb[d * Dc + j];
                y0 = fmaf(xs[d],          w, y0);
                y1 = fmaf(xs[Dc + d],     w, y1);
                y2 = fmaf(xs[2 * Dc + d], w, y2);
                y3 = fmaf(xs[3 * Dc + d], w, y3);
            }
            oy[(b0 + 0) * Dc + j] = sigf(y0);
            oy[(b0 + 1) * Dc + j] = sigf(y1);
            oy[(b0 + 2) * Dc + j] = sigf(y2);
            oy[(b0 + 3) * Dc + j] = sigf(y3);
        }
    }

    // ---------------- ticket-balanced streaming copy (all blocks) ----------
    const float4* __restrict__ src = reinterpret_cast<const float4*>(hist);
    float4*       __restrict__ dst = reinterpret_cast<float4*>(ohist);
    for (;;) {
        __syncthreads();
        if (j == 0) s_t = atomicAdd(&g_ticket, 1u);
        __syncthreads();
        const unsigned u = s_t;
        if (u >= NUNITS) break;
        const long long base = (long long)u * UNIT + j;
        #pragma unroll
        for (int q4 = 0; q4 < 4; ++q4) {
            const long long i0 = base + (q4 * 4 + 0) * 256;
            const long long i1 = base + (q4 * 4 + 1) * 256;
            const long long i2 = base + (q4 * 4 + 2) * 256;
            const long long i3 = base + (q4 * 4 + 3) * 256;
            const float4 v0 = __ldcs(src + i0);
            const float4 v1 = __ldcs(src + i1);
            const float4 v2 = __ldcs(src + i2);
            const float4 v3 = __ldcs(src + i3);
            if ((int)((i0 >> 6) & (Tc - 1)) != cur) __stcs(dst + i0, v0);
            if ((int)((i1 >> 6) & (Tc - 1)) != cur) __stcs(dst + i1, v1);
            if ((int)((i2 >> 6) & (Tc - 1)) != cur) __stcs(dst + i2, v2);
            if ((int)((i3 >> 6) & (Tc - 1)) != cur) __stcs(dst + i3, v3);
        }
    }
}

} // namespace

extern "C" void kernel_launch(void* const* d_in, const int* in_sizes, int n_in,
                              void* d_out, int out_size)
{
    const float* x    = (const float*)d_in[0];
    const float* hist = (const float*)d_in[1];
    const float* Wi   = (const float*)d_in[2];
    const float* bi   = (const float*)d_in[3];
    const float* Wk   = (const float*)d_in[4];
    // d_in[5] = bk — dropped: constant over m, softmax-shift invariant
    const float* Wv   = (const float*)d_in[6];
    const float* bv   = (const float*)d_in[7];
    const float* Wb   = (const float*)d_in[8];
    const float* bb   = (const float*)d_in[9];
    const int*   jp   = (const int*)d_in[10];
    const int*   cur  = (const int*)d_in[11];

    float* out   = (float*)d_out;
    float* oh    = out;                    // h:  [B, D]
    float* oy    = out + Bc * Dc;          // y:  [B, D]
    float* ohist = out + 2 * Bc * Dc;      // new_history: [B, T, D]

    (void)in_sizes; (void)n_in; (void)out_size;

    // 0) transpose Wk + reset copy ticket (graph-replay safe)
    bjrnn_prep<<<dim3(Dc / 32, Dc / 32), 256>>>(Wk);

    // 1) fused compute + ticket-balanced full-occupancy copy
    bjrnn_fused<<<GRID, 256>>>(
        x, hist, Wi, bi, Wv, bv, Wb, bb, jp, cur, oh, oy, ohist);
}